// round 5
// baseline (speedup 1.0000x reference)
#include <cuda_runtime.h>
#include <math.h>

// Shapes fixed per reference: B=8192, D=128, R=64, C=64.
// Strategy: exp(logit) underflows to exact 0 for all but a tiny fraction of the
// 524288 (b,r) pairs, so compute firing strengths exactly, compact nonzero
// pairs per rule, and run a small gathered per-rule GEMV. Everything is fused
// into ONE persistent kernel (launch overhead ~8us/kernel dominated prior
// rounds) with software grid barriers between phases.

#define NB 148                           // grid size == persistent blocks

// ---------------- device scratch ----------------
__device__ float    g_psum[128 * NB];    // BN partial sums [d][blk]
__device__ float    g_psq [128 * NB];    // BN partial sumsq [d][blk]
__device__ float2   g_scsh[128];         // per-d (scale, shift)
__device__ float4   g_coef[128 * 32];    // [d][lane] = (u_l, m_l, u_{l+32}, m_{l+32})
__device__ float    g_csum[64];          // per-rule sum_d c^2 u
__device__ int      g_count[64];         // nonzero rows per rule
__device__ int      g_rows [64 * 8192];
__device__ float    g_fvals[64 * 8192];
__device__ unsigned g_bar1, g_bar2;      // monotone barrier tickets (replay-safe)

__device__ __forceinline__ void grid_barrier(unsigned* ctr, bool wait) {
    __syncthreads();
    if (threadIdx.x == 0) {
        __threadfence();                               // release my writes
        unsigned t = atomicAdd(ctr, 1u);
        unsigned target = t - (t % NB) + NB;           // launch's generation end
        if (wait) {
            while (*(volatile unsigned*)ctr < target) {}
            __threadfence();                           // acquire others' writes
        }
    }
    __syncthreads();
}

__global__ void __launch_bounds__(256, 1)
fused_all(const float* __restrict__ x,
          const float* __restrict__ centers,
          const float* __restrict__ sigmas,
          const float* __restrict__ weights,
          const float* __restrict__ biases,
          const float* __restrict__ gamma,
          const float* __restrict__ beta,
          const float* __restrict__ rule_masks,
          float* __restrict__ out) {
    extern __shared__ float4 dyn4[];     // P2: coef copy (64KB). P3: W tile (32KB).
    __shared__ float ps[256], ps2[256];
    __shared__ float2 scsh_s[128];
    __shared__ float  bias_s[64];

    int tid = threadIdx.x, blk = blockIdx.x;
    int lane = tid & 31, wid = tid >> 5;

    // ================= P1: zero out + BN partials + coef pack =================
    float4 z4 = make_float4(0.f, 0.f, 0.f, 0.f);
    float4* out4 = (float4*)out;
    for (int c = blk; c < 512; c += NB) out4[c * 256 + tid] = z4;   // 2MB zero
    if (blk == 0 && tid < 64) g_count[tid] = 0;

    float s = 0.f, s2 = 0.f;
    for (int c = blk; c < 4096; c += NB) {       // d = tid & 127 invariant
        float v = x[c * 256 + tid];
        s += v; s2 += v * v;
    }
    ps[tid] = s; ps2[tid] = s2;
    __syncthreads();
    if (tid < 128) {
        g_psum[tid * NB + blk] = ps[tid] + ps[tid + 128];
        g_psq [tid * NB + blk] = ps2[tid] + ps2[tid + 128];
    }

    if (blk == 0) {
        // pack quadratic coefficients (parallel, 16 float4 per thread)
        #pragma unroll
        for (int k = 0; k < 16; ++k) {
            int f = k * 256 + tid;               // f = d*32 + ln
            int d = f >> 5, ln = f & 31;
            float c0 = centers[d * 64 + ln],      s0 = sigmas[d * 64 + ln];
            float c1 = centers[d * 64 + ln + 32], s1 = sigmas[d * 64 + ln + 32];
            float u0 = 1.0f / (2.0f * s0 * s0);
            float u1 = 1.0f / (2.0f * s1 * s1);
            g_coef[f] = make_float4(u0, -2.0f * c0 * u0, u1, -2.0f * c1 * u1);
        }
        // per-rule csum = sum_d c^2 u, parallel: r = tid&63, quarter q = tid>>6
        int r = tid & 63, q = tid >> 6;
        float cs = 0.f;
        #pragma unroll 8
        for (int dd = 0; dd < 32; ++dd) {
            int d = q * 32 + dd;
            float c = centers[d * 64 + r], sg = sigmas[d * 64 + r];
            cs = fmaf(c * c, 1.0f / (2.0f * sg * sg), cs);
        }
        __syncthreads();                         // ps free for reuse
        ps[tid] = cs;
        __syncthreads();
        if (tid < 64)
            g_csum[tid] = (ps[tid] + ps[tid + 64]) + (ps[tid + 128] + ps[tid + 192]);
    }

    grid_barrier(&g_bar1, true);

    // ================= P2: BN finalize (block 0) + firing strengths =================
    if (blk == 0) {
        int d = tid >> 1, half = tid & 1;        // 2 threads per d, 74 partials each
        const float* pp = g_psum + d * NB + half * 74;
        const float* pq = g_psq  + d * NB + half * 74;
        float ss = 0.f, qq = 0.f;
        #pragma unroll 8
        for (int k = 0; k < 74; ++k) { ss += pp[k]; qq += pq[k]; }
        ss += __shfl_xor_sync(0xffffffffu, ss, 1);
        qq += __shfl_xor_sync(0xffffffffu, qq, 1);
        if (half == 0) {
            float mean = ss * (1.0f / 8192.0f);
            float var  = fmaxf(qq * (1.0f / 8192.0f) - mean * mean, 0.0f);
            float sc = gamma[d] / sqrtf(var + 1e-5f);
            g_scsh[d] = make_float2(sc, beta[d] - mean * sc);
        }
    }

    for (int k = tid; k < 4096; k += 256) dyn4[k] = g_coef[k];
    __syncthreads();

    {
        float m0 = rule_masks[lane];
        float m1 = rule_masks[lane + 32];
        float cs0 = g_csum[lane];
        float cs1 = g_csum[lane + 32];
        int w = blk * 8 + wid;                   // [0, 1184)

        for (int p = w; p < 4096; p += NB * 8) {
            int b0 = 2 * p, b1 = 2 * p + 1;
            const float* xr0 = x + (size_t)b0 * 128;
            const float* xr1 = x + (size_t)b1 * 128;
            float xq0[4], xq1[4];
            #pragma unroll
            for (int j = 0; j < 4; ++j) {
                xq0[j] = xr0[j * 32 + lane];
                xq1[j] = xr1[j * 32 + lane];
            }
            float a00 = 0.f, a01 = 0.f, a10 = 0.f, a11 = 0.f;
            #pragma unroll
            for (int j = 0; j < 4; ++j) {
                float xv0 = xq0[j], xv1 = xq1[j];
                #pragma unroll 8
                for (int t = 0; t < 32; ++t) {
                    float xd0 = __shfl_sync(0xffffffffu, xv0, t);
                    float xd1 = __shfl_sync(0xffffffffu, xv1, t);
                    float x20 = xd0 * xd0;
                    float x21 = xd1 * xd1;
                    float4 cf = dyn4[(j * 32 + t) * 32 + lane];
                    a00 = fmaf(x20, cf.x, a00); a00 = fmaf(xd0, cf.y, a00);
                    a01 = fmaf(x20, cf.z, a01); a01 = fmaf(xd0, cf.w, a01);
                    a10 = fmaf(x21, cf.x, a10); a10 = fmaf(xd1, cf.y, a10);
                    a11 = fmaf(x21, cf.z, a11); a11 = fmaf(xd1, cf.w, a11);
                }
            }
            float r00 = expf(-(a00 + cs0)) * m0, r01 = expf(-(a01 + cs1)) * m1;
            float r10 = expf(-(a10 + cs0)) * m0, r11 = expf(-(a11 + cs1)) * m1;
            float s0 = r00 + r01, s1 = r10 + r11;
            #pragma unroll
            for (int off = 16; off; off >>= 1) {
                s0 += __shfl_xor_sync(0xffffffffu, s0, off);
                s1 += __shfl_xor_sync(0xffffffffu, s1, off);
            }
            float den0 = s0 + 1e-10f, den1 = s1 + 1e-10f;
            float f00 = r00 / den0, f01 = r01 / den0;
            float f10 = r10 / den1, f11 = r11 / den1;
            if (f00 > 0.f) { int q = atomicAdd(&g_count[lane], 1);
                             g_rows[lane * 8192 + q] = b0; g_fvals[lane * 8192 + q] = f00; }
            if (f01 > 0.f) { int q = atomicAdd(&g_count[lane + 32], 1);
                             g_rows[(lane + 32) * 8192 + q] = b0; g_fvals[(lane + 32) * 8192 + q] = f01; }
            if (f10 > 0.f) { int q = atomicAdd(&g_count[lane], 1);
                             g_rows[lane * 8192 + q] = b1; g_fvals[lane * 8192 + q] = f10; }
            if (f11 > 0.f) { int q = atomicAdd(&g_count[lane + 32], 1);
                             g_rows[(lane + 32) * 8192 + q] = b1; g_fvals[(lane + 32) * 8192 + q] = f11; }
        }
    }

    grid_barrier(&g_bar2, blk < 128);            // blocks >=128 arrive and leave
    if (blk >= 128) return;

    // ================= P3: gathered per-rule GEMV (2 blocks / rule) =================
    int r = blk >> 1, half = blk & 1;
    const float4* Wg = (const float4*)(weights + (size_t)r * 8192);
    #pragma unroll
    for (int k = 0; k < 8; ++k) dyn4[k * 256 + tid] = Wg[k * 256 + tid];  // 32KB W
    if (tid < 128) scsh_s[tid] = g_scsh[tid];
    if (tid < 64)  bias_s[tid] = biases[r * 64 + tid];
    __syncthreads();

    int cnt = g_count[r];
    const float* Ws = (const float*)dyn4;
    int c = lane * 2;

    for (int i = half * 8 + wid; i < cnt; i += 16) {
        int b   = g_rows [r * 8192 + i];
        float f = g_fvals[r * 8192 + i];
        float xnv[4];
        #pragma unroll
        for (int j = 0; j < 4; ++j) {
            float2 ss = scsh_s[j * 32 + lane];
            xnv[j] = x[(size_t)b * 128 + j * 32 + lane] * ss.x + ss.y;
        }
        float a0 = 0.f, a1 = 0.f;
        #pragma unroll
        for (int j = 0; j < 4; ++j) {
            float xv = xnv[j];
            #pragma unroll 8
            for (int t = 0; t < 32; ++t) {
                float xk = __shfl_sync(0xffffffffu, xv, t);
                float2 w = *(const float2*)(Ws + (j * 32 + t) * 64 + c);
                a0 = fmaf(xk, w.x, a0);
                a1 = fmaf(xk, w.y, a1);
            }
        }
        atomicAdd(out + (size_t)b * 64 + c,     f * (a0 + bias_s[c]));
        atomicAdd(out + (size_t)b * 64 + c + 1, f * (a1 + bias_s[c + 1]));
    }
}

// ---------------- launch ----------------
extern "C" void kernel_launch(void* const* d_in, const int* in_sizes, int n_in,
                              void* d_out, int out_size) {
    const float* x       = (const float*)d_in[0];
    const float* centers = (const float*)d_in[1];
    const float* sigmas  = (const float*)d_in[2];
    const float* weights = (const float*)d_in[3];
    const float* biases  = (const float*)d_in[4];
    const float* gamma   = (const float*)d_in[5];
    const float* beta    = (const float*)d_in[6];
    const float* masks   = (const float*)d_in[7];
    float* out = (float*)d_out;

    cudaFuncSetAttribute(fused_all, cudaFuncAttributeMaxDynamicSharedMemorySize, 65536);
    fused_all<<<NB, 256, 65536>>>(x, centers, sigmas, weights, biases,
                                  gamma, beta, masks, out);
}

// round 6
// speedup vs baseline: 2.2637x; 2.2637x over previous
#include <cuda_runtime.h>
#include <math.h>

// Shapes fixed: B=8192, D=128, R=64, C=64.
// exp(logit) underflows to ~0 for all but ~10^3 of 524288 (b,r) pairs; the
// softmax denominator is dominated by the +1e-10 term. Compute frs in the same
// fp32 formulation, compact nonzero pairs per rule, gathered per-rule GEMV.
// Three kernels, each shaped for occupancy (fused single-kernel variant proved
// 2x slower: frs phase is issue-bound and needs 32 warps/SM, not 8).

// ---------------- device scratch ----------------
__device__ float  g_psum[128 * 256];     // BN partial sums  [d][blk]
__device__ float  g_psq [128 * 256];     // BN partial sumsq [d][blk]
__device__ float2 g_scsh[128];           // per-d (scale, shift)
__device__ float4 g_coef[4096];          // [d][lane] = (u_l, m_l, u_{l+32}, m_{l+32})
__device__ float  g_csum[64];            // per-rule sum_d c^2 u
__device__ int    g_count[64];           // nonzero rows per rule
__device__ int    g_rows [64 * 8192];
__device__ float  g_fvals[64 * 8192];

// ---------------- kA: zero out + BN partials + coef pack + csum ----------------
// grid 256, block 256
__global__ void kA_prep(const float* __restrict__ x,
                        const float* __restrict__ centers,
                        const float* __restrict__ sigmas,
                        float4* __restrict__ out4) {
    __shared__ float ps[256], ps2[256];
    int blk = blockIdx.x, tid = threadIdx.x;

    // zero output: 131072 float4 / 256 blocks = 2 per thread
    float4 z4 = make_float4(0.f, 0.f, 0.f, 0.f);
    out4[blk * 512 + tid]       = z4;
    out4[blk * 512 + 256 + tid] = z4;

    // BN partial sums over rows [blk*32, blk*32+32)
    const float* xp = x + (size_t)blk * 32 * 128;
    float s = 0.f, s2 = 0.f;
    #pragma unroll
    for (int it = 0; it < 16; ++it) {
        float v = xp[it * 256 + tid];    // d = tid & 127 invariant over it
        s += v; s2 += v * v;
    }
    ps[tid] = s; ps2[tid] = s2;
    __syncthreads();
    if (tid < 128) {
        g_psum[tid * 256 + blk] = ps[tid] + ps[tid + 128];   // [d][blk]
        g_psq [tid * 256 + blk] = ps2[tid] + ps2[tid + 128];
    }
    __syncthreads();

    if (blk == 0) {
        if (tid < 64) g_count[tid] = 0;
        // pack quadratic coefficients: 4096 float4, 16 per thread
        #pragma unroll
        for (int k = 0; k < 16; ++k) {
            int f = k * 256 + tid;               // f = d*32 + ln
            int d = f >> 5, ln = f & 31;
            float c0 = centers[d * 64 + ln],      s0 = sigmas[d * 64 + ln];
            float c1 = centers[d * 64 + ln + 32], s1 = sigmas[d * 64 + ln + 32];
            float u0 = 1.0f / (2.0f * s0 * s0);
            float u1 = 1.0f / (2.0f * s1 * s1);
            g_coef[f] = make_float4(u0, -2.0f * c0 * u0, u1, -2.0f * c1 * u1);
        }
        // per-rule csum = sum_d c^2 u (parallel: r = tid&63, quarter q = tid>>6)
        int r = tid & 63, q = tid >> 6;
        float cs = 0.f;
        #pragma unroll 8
        for (int dd = 0; dd < 32; ++dd) {
            int d = q * 32 + dd;
            float c = centers[d * 64 + r], sg = sigmas[d * 64 + r];
            cs = fmaf(c * c, 1.0f / (2.0f * sg * sg), cs);
        }
        __syncthreads();
        ps[tid] = cs;
        __syncthreads();
        if (tid < 64)
            g_csum[tid] = (ps[tid] + ps[tid + 64]) + (ps[tid + 128] + ps[tid + 192]);
    }
}

// ---------------- kC: firing strengths + per-rule compaction ----------------
// grid 129, block 1024 (32 warps). Blocks 0-127: one warp per row-pair
// (128*32 = 4096 pairs, no loop). Block 128: BN finalize only.
__global__ void __launch_bounds__(1024)
kC_frs(const float* __restrict__ x,
       const float* __restrict__ rule_masks,
       const float* __restrict__ gamma,
       const float* __restrict__ beta) {
    int tid = threadIdx.x, blk = blockIdx.x;

    if (blk == 128) {
        // BN finalize: 8 threads per d, each sums 32 slots (8 float4 loads)
        int d = tid >> 3, s8 = tid & 7;
        const float4* p4 = (const float4*)(g_psum + d * 256 + s8 * 32);
        const float4* q4 = (const float4*)(g_psq  + d * 256 + s8 * 32);
        float ss = 0.f, qq = 0.f;
        #pragma unroll
        for (int k = 0; k < 8; ++k) {
            float4 a = p4[k]; ss += (a.x + a.y) + (a.z + a.w);
            float4 b = q4[k]; qq += (b.x + b.y) + (b.z + b.w);
        }
        #pragma unroll
        for (int off = 4; off; off >>= 1) {
            ss += __shfl_down_sync(0xffffffffu, ss, off, 8);
            qq += __shfl_down_sync(0xffffffffu, qq, off, 8);
        }
        if (s8 == 0) {
            float mean = ss * (1.0f / 8192.0f);
            float var  = fmaxf(qq * (1.0f / 8192.0f) - mean * mean, 0.0f);
            float sc = gamma[d] / sqrtf(var + 1e-5f);
            g_scsh[d] = make_float2(sc, beta[d] - mean * sc);
        }
        return;
    }

    extern __shared__ float4 cs4[];      // coef copy, 4096 float4 = 64KB
    #pragma unroll
    for (int k = 0; k < 4; ++k) cs4[k * 1024 + tid] = g_coef[k * 1024 + tid];
    __syncthreads();

    int lane = tid & 31, wid = tid >> 5;
    float m0 = rule_masks[lane];
    float m1 = rule_masks[lane + 32];
    float cc0 = g_csum[lane];
    float cc1 = g_csum[lane + 32];

    int p = blk * 32 + wid;              // unique pair per warp
    int b0 = 2 * p, b1 = 2 * p + 1;
    const float* xr0 = x + (size_t)b0 * 128;
    const float* xr1 = x + (size_t)b1 * 128;
    float xq0[4], xq1[4];
    #pragma unroll
    for (int j = 0; j < 4; ++j) {
        xq0[j] = xr0[j * 32 + lane];
        xq1[j] = xr1[j * 32 + lane];
    }
    float a00 = 0.f, a01 = 0.f, a10 = 0.f, a11 = 0.f;
    #pragma unroll
    for (int j = 0; j < 4; ++j) {
        float xv0 = xq0[j], xv1 = xq1[j];
        #pragma unroll 8
        for (int t = 0; t < 32; ++t) {
            float xd0 = __shfl_sync(0xffffffffu, xv0, t);
            float xd1 = __shfl_sync(0xffffffffu, xv1, t);
            float x20 = xd0 * xd0;
            float x21 = xd1 * xd1;
            float4 cf = cs4[(j * 32 + t) * 32 + lane];
            a00 = fmaf(x20, cf.x, a00); a00 = fmaf(xd0, cf.y, a00);
            a01 = fmaf(x20, cf.z, a01); a01 = fmaf(xd0, cf.w, a01);
            a10 = fmaf(x21, cf.x, a10); a10 = fmaf(xd1, cf.y, a10);
            a11 = fmaf(x21, cf.z, a11); a11 = fmaf(xd1, cf.w, a11);
        }
    }
    float r00 = __expf(-(a00 + cc0)) * m0, r01 = __expf(-(a01 + cc1)) * m1;
    float r10 = __expf(-(a10 + cc0)) * m0, r11 = __expf(-(a11 + cc1)) * m1;
    float s0 = r00 + r01, s1 = r10 + r11;
    #pragma unroll
    for (int off = 16; off; off >>= 1) {
        s0 += __shfl_xor_sync(0xffffffffu, s0, off);
        s1 += __shfl_xor_sync(0xffffffffu, s1, off);
    }
    float den0 = s0 + 1e-10f, den1 = s1 + 1e-10f;
    float f00 = r00 / den0, f01 = r01 / den0;
    float f10 = r10 / den1, f11 = r11 / den1;
    if (f00 > 0.f) { int q = atomicAdd(&g_count[lane], 1);
                     g_rows[lane * 8192 + q] = b0; g_fvals[lane * 8192 + q] = f00; }
    if (f01 > 0.f) { int q = atomicAdd(&g_count[lane + 32], 1);
                     g_rows[(lane + 32) * 8192 + q] = b0; g_fvals[(lane + 32) * 8192 + q] = f01; }
    if (f10 > 0.f) { int q = atomicAdd(&g_count[lane], 1);
                     g_rows[lane * 8192 + q] = b1; g_fvals[lane * 8192 + q] = f10; }
    if (f11 > 0.f) { int q = atomicAdd(&g_count[lane + 32], 1);
                     g_rows[(lane + 32) * 8192 + q] = b1; g_fvals[(lane + 32) * 8192 + q] = f11; }
}

// ---------------- kD: per-rule gathered GEMV, W staged in smem ----------------
// grid (2, 64), block 256 (8 warps). Lane covers 2 output cols.
__global__ void kD_out(const float* __restrict__ x,
                       const float* __restrict__ weights,
                       const float* __restrict__ biases,
                       float* __restrict__ out) {
    int r = blockIdx.y;
    __shared__ float4 Ws4[2048];         // W[r]: 32KB
    __shared__ float2 scsh[128];
    __shared__ float  bias_s[64];
    int tid = threadIdx.x;
    const float4* Wg = (const float4*)(weights + (size_t)r * 8192);
    #pragma unroll
    for (int k = 0; k < 8; ++k) Ws4[k * 256 + tid] = Wg[k * 256 + tid];
    if (tid < 128) scsh[tid] = g_scsh[tid];
    if (tid < 64)  bias_s[tid] = biases[r * 64 + tid];
    __syncthreads();

    int cnt = g_count[r];
    const float* Ws = (const float*)Ws4;
    int lane = tid & 31, wid = tid >> 5;
    int c = lane * 2;

    for (int i = blockIdx.x * 8 + wid; i < cnt; i += 16) {
        int b   = g_rows [r * 8192 + i];
        float f = g_fvals[r * 8192 + i];
        float xnv[4];
        #pragma unroll
        for (int j = 0; j < 4; ++j) {
            float2 ss = scsh[j * 32 + lane];
            xnv[j] = x[(size_t)b * 128 + j * 32 + lane] * ss.x + ss.y;
        }
        float a0 = 0.f, a1 = 0.f;
        #pragma unroll
        for (int j = 0; j < 4; ++j) {
            float xv = xnv[j];
            #pragma unroll 8
            for (int t = 0; t < 32; ++t) {
                float xk = __shfl_sync(0xffffffffu, xv, t);
                float2 w = *(const float2*)(Ws + (j * 32 + t) * 64 + c);
                a0 = fmaf(xk, w.x, a0);
                a1 = fmaf(xk, w.y, a1);
            }
        }
        atomicAdd(out + (size_t)b * 64 + c,     f * (a0 + bias_s[c]));
        atomicAdd(out + (size_t)b * 64 + c + 1, f * (a1 + bias_s[c + 1]));
    }
}

// ---------------- launch ----------------
extern "C" void kernel_launch(void* const* d_in, const int* in_sizes, int n_in,
                              void* d_out, int out_size) {
    const float* x       = (const float*)d_in[0];
    const float* centers = (const float*)d_in[1];
    const float* sigmas  = (const float*)d_in[2];
    const float* weights = (const float*)d_in[3];
    const float* biases  = (const float*)d_in[4];
    const float* gamma   = (const float*)d_in[5];
    const float* beta    = (const float*)d_in[6];
    const float* masks   = (const float*)d_in[7];
    float* out = (float*)d_out;

    cudaFuncSetAttribute(kC_frs, cudaFuncAttributeMaxDynamicSharedMemorySize, 65536);

    kA_prep<<<256, 256>>>(x, centers, sigmas, (float4*)out);
    kC_frs<<<129, 1024, 65536>>>(x, masks, gamma, beta);
    dim3 gD(2, 64);
    kD_out<<<gD, 256>>>(x, weights, biases, out);
}